// round 1
// baseline (speedup 1.0000x reference)
#include <cuda_runtime.h>
#include <cstdint>

#define Bn 2
#define Cn 64
#define Hn 384
#define Wn 384
#define Gn 4
#define GCn 16
#define OMD 112   // Wom columns
#define OMS 108   // used off/mask channels
#define TILES_X (Wn/64)           // 6
#define NTILE (Bn*Hn*TILES_X)     // 4608
#define HW (Hn*Wn)

__device__ __align__(16) float g_value[Bn*HW*Cn];     // [b,h,w,c]  NHWC
__device__ __align__(16) float g_offmask[Bn*HW*OMS];  // [b,h,w,108]

// ---------------------------------------------------------------------------
// Kernel 1: value = NHWC(inp) @ Wv + bv   -> g_value
// ---------------------------------------------------------------------------
__global__ __launch_bounds__(256) void k_value(const float* __restrict__ inp,
                                               const float* __restrict__ Wv,
                                               const float* __restrict__ bv) {
    __shared__ float x_s[64*64];  // [k(ch)][p(pixel)]
    __shared__ float w_s[64*64];  // [k][c]
    int t  = blockIdx.x;
    int w0 = (t % TILES_X) * 64;
    int h  = (t / TILES_X) % Hn;
    int b  = t / (TILES_X * Hn);
    int tid = threadIdx.x;

    const float* src = inp + (size_t)b*Cn*HW + (size_t)h*Wn + w0;
    #pragma unroll
    for (int i = tid; i < 4096; i += 256) {
        int c = i >> 6, p = i & 63;
        x_s[i] = src[(size_t)c*HW + p];
        w_s[i] = Wv[i];
    }
    __syncthreads();

    int ty = tid >> 4, tx = tid & 15;   // ty -> pixel group, tx -> channel group
    float acc[4][4];
    #pragma unroll
    for (int i = 0; i < 4; i++)
        #pragma unroll
        for (int j = 0; j < 4; j++) acc[i][j] = 0.f;

    const float4* x4 = (const float4*)x_s;
    const float4* w4 = (const float4*)w_s;
    #pragma unroll
    for (int k = 0; k < 64; k++) {
        float4 a  = x4[k*16 + ty];   // 4 pixels
        float4 bb = w4[k*16 + tx];   // 4 channels
        float av[4] = {a.x, a.y, a.z, a.w};
        float bw[4] = {bb.x, bb.y, bb.z, bb.w};
        #pragma unroll
        for (int i = 0; i < 4; i++)
            #pragma unroll
            for (int j = 0; j < 4; j++)
                acc[i][j] = fmaf(av[i], bw[j], acc[i][j]);
    }
    float4 bias = *(const float4*)(bv + tx*4);
    int pixbase = (b*Hn + h)*Wn + w0;
    #pragma unroll
    for (int i = 0; i < 4; i++) {
        float4 v = make_float4(acc[i][0]+bias.x, acc[i][1]+bias.y,
                               acc[i][2]+bias.z, acc[i][3]+bias.w);
        *(float4*)(g_value + (size_t)(pixbase + ty*4 + i)*64 + tx*4) = v;
    }
}

// ---------------------------------------------------------------------------
// Kernel 2: dw = depthwise3x3(inp)+bdw ; om = dw @ Wom[:, :108] + bom
//           -> g_offmask
// smem layout (floats): t_in[64*3*66]=12672 | wdw[576] | wom[7168]  = 20416
// t_in region is reused as dw_s[64*64] after the depthwise pass.
// ---------------------------------------------------------------------------
__global__ __launch_bounds__(256) void k_offmask(const float* __restrict__ inp,
                                                 const float* __restrict__ Wdw,
                                                 const float* __restrict__ bdw,
                                                 const float* __restrict__ Wom,
                                                 const float* __restrict__ bom) {
    extern __shared__ float sm[];
    float* t_in  = sm;                 // [c][r][66]
    float* wdw_s = sm + 12672;         // [c][9]
    float* wom_s = sm + 12672 + 576;   // [k][112]

    int t  = blockIdx.x;
    int w0 = (t % TILES_X) * 64;
    int h  = (t / TILES_X) % Hn;
    int b  = t / (TILES_X * Hn);
    int tid = threadIdx.x;

    for (int i = tid; i < 576;  i += 256) wdw_s[i] = Wdw[i];
    for (int i = tid; i < 7168; i += 256) wom_s[i] = Wom[i];

    const float* src = inp + (size_t)b*Cn*HW;
    for (int i = tid; i < 64*3*66; i += 256) {
        int c   = i / 198;
        int rem = i - c*198;
        int r   = rem / 66;
        int pw  = rem - r*66;
        int hh  = h - 1 + r;
        int ww  = w0 - 1 + pw;
        float v = 0.f;
        if ((unsigned)hh < (unsigned)Hn && (unsigned)ww < (unsigned)Wn)
            v = src[(size_t)c*HW + (size_t)hh*Wn + ww];
        t_in[i] = v;
    }
    __syncthreads();

    // depthwise conv, results in registers
    float dwreg[16];
    #pragma unroll
    for (int ii = 0; ii < 16; ii++) {
        int item = tid + 256*ii;
        int c = item >> 6, p = item & 63;
        float a = __ldg(&bdw[c]);
        const float* ti = t_in + c*198;
        const float* wd = wdw_s + c*9;
        #pragma unroll
        for (int r = 0; r < 3; r++)
            #pragma unroll
            for (int kx = 0; kx < 3; kx++)
                a = fmaf(ti[r*66 + p + kx], wd[r*3 + kx], a);
        dwreg[ii] = a;
    }
    __syncthreads();          // all reads of t_in complete
    float* dw_s = sm;         // reuse region: [c][p]
    #pragma unroll
    for (int ii = 0; ii < 16; ii++)
        dw_s[tid + 256*ii] = dwreg[ii];
    __syncthreads();

    // om GEMM: 64 pixels x 108 cols, thread = 4 pixels x 7 cols
    int ty = tid >> 4, tx = tid & 15;
    float acc[4][7];
    #pragma unroll
    for (int i = 0; i < 4; i++)
        #pragma unroll
        for (int j = 0; j < 7; j++) acc[i][j] = 0.f;

    const float4* d4 = (const float4*)dw_s;
    #pragma unroll
    for (int k = 0; k < 64; k++) {
        float4 a = d4[k*16 + ty];
        float av[4] = {a.x, a.y, a.z, a.w};
        float bw[7];
        #pragma unroll
        for (int jj = 0; jj < 7; jj++) bw[jj] = wom_s[k*112 + tx*7 + jj];
        #pragma unroll
        for (int i = 0; i < 4; i++)
            #pragma unroll
            for (int jj = 0; jj < 7; jj++)
                acc[i][jj] = fmaf(av[i], bw[jj], acc[i][jj]);
    }
    int pixbase = (b*Hn + h)*Wn + w0;
    #pragma unroll
    for (int i = 0; i < 4; i++) {
        float* dst = g_offmask + (size_t)(pixbase + ty*4 + i)*OMS;
        #pragma unroll
        for (int jj = 0; jj < 7; jj++) {
            int j = tx*7 + jj;
            if (j < OMS) dst[j] = acc[i][jj] + __ldg(&bom[j]);
        }
    }
}

// ---------------------------------------------------------------------------
// Kernel 3: deformable sampling + (out @ Wo), store NCHW
// smem (floats): om_s[64*108]=6912 | out_s[64*64]=4096 ([ch][p]) | wo_s[4096]
// ---------------------------------------------------------------------------
__global__ __launch_bounds__(256) void k_sample(const float* __restrict__ Wo,
                                                float* __restrict__ out) {
    extern __shared__ float sm[];
    float* om_s  = sm;                // [p][108]
    float* out_s = sm + 6912;         // [k(ch)][p]
    float* wo_s  = sm + 6912 + 4096;  // [k][c]

    int t  = blockIdx.x;
    int w0 = (t % TILES_X) * 64;
    int h  = (t / TILES_X) % Hn;
    int b  = t / (TILES_X * Hn);
    int tid = threadIdx.x;
    int pixbase = (b*Hn + h)*Wn + w0;

    const float4* omsrc = (const float4*)(g_offmask + (size_t)pixbase*OMS);
    float4* omdst = (float4*)om_s;
    for (int i = tid; i < 64*OMS/4; i += 256) omdst[i] = omsrc[i];
    for (int i = tid; i < 4096; i += 256) wo_s[i] = Wo[i];
    __syncthreads();

    // ---- phase 1: sampling. thread = (pixel p, group g), g fastest in warp
    int g = tid & 3, p = tid >> 2;
    float o[27];
    const float* ob = om_s + p*OMS + g*27;
    #pragma unroll
    for (int i = 0; i < 27; i++) o[i] = ob[i];

    float acc[16];
    #pragma unroll
    for (int i = 0; i < 16; i++) acc[i] = 0.f;

    float fw = (float)(w0 + p);
    float fh = (float)h;
    const float* vbase = g_value + (size_t)b*HW*64 + g*16;

    #pragma unroll
    for (int k = 0; k < 9; k++) {
        int ky = k / 3, kx = k - ky*3;
        float px = fw + (float)(kx - 1) + o[2*k];
        float py = fh + (float)(ky - 1) + o[2*k + 1];
        float m  = o[18 + k];
        float x0f = floorf(px), y0f = floorf(py);
        float fx = px - x0f, fy = py - y0f;
        int x0 = (int)x0f, y0 = (int)y0f;
        #pragma unroll
        for (int dyc = 0; dyc < 2; dyc++) {
            #pragma unroll
            for (int dxc = 0; dxc < 2; dxc++) {
                int xi = x0 + dxc, yi = y0 + dyc;
                float wgt = m * (dyc ? fy : 1.f - fy) * (dxc ? fx : 1.f - fx);
                if ((unsigned)xi >= (unsigned)Wn || (unsigned)yi >= (unsigned)Hn)
                    wgt = 0.f;
                int xc = min(max(xi, 0), Wn - 1);
                int yc = min(max(yi, 0), Hn - 1);
                const float4* vp =
                    (const float4*)(vbase + ((size_t)yc*Wn + xc)*64);
                float4 v0 = vp[0], v1 = vp[1], v2 = vp[2], v3 = vp[3];
                acc[0]  = fmaf(wgt, v0.x, acc[0]);
                acc[1]  = fmaf(wgt, v0.y, acc[1]);
                acc[2]  = fmaf(wgt, v0.z, acc[2]);
                acc[3]  = fmaf(wgt, v0.w, acc[3]);
                acc[4]  = fmaf(wgt, v1.x, acc[4]);
                acc[5]  = fmaf(wgt, v1.y, acc[5]);
                acc[6]  = fmaf(wgt, v1.z, acc[6]);
                acc[7]  = fmaf(wgt, v1.w, acc[7]);
                acc[8]  = fmaf(wgt, v2.x, acc[8]);
                acc[9]  = fmaf(wgt, v2.y, acc[9]);
                acc[10] = fmaf(wgt, v2.z, acc[10]);
                acc[11] = fmaf(wgt, v2.w, acc[11]);
                acc[12] = fmaf(wgt, v3.x, acc[12]);
                acc[13] = fmaf(wgt, v3.y, acc[13]);
                acc[14] = fmaf(wgt, v3.z, acc[14]);
                acc[15] = fmaf(wgt, v3.w, acc[15]);
            }
        }
    }
    #pragma unroll
    for (int cc = 0; cc < 16; cc++)
        out_s[(g*16 + cc)*64 + p] = acc[cc];
    __syncthreads();

    // ---- phase 2: out2[c][p] = sum_k wo_s[k][c] * out_s[k][p], store NCHW
    int ty = tid >> 4, tx = tid & 15;  // ty -> channel group, tx -> pixel group
    float a2[4][4];
    #pragma unroll
    for (int i = 0; i < 4; i++)
        #pragma unroll
        for (int j = 0; j < 4; j++) a2[i][j] = 0.f;

    const float4* W4 = (const float4*)wo_s;
    const float4* O4 = (const float4*)out_s;
    #pragma unroll
    for (int k = 0; k < 64; k++) {
        float4 a  = W4[k*16 + ty];   // 4 channels
        float4 bb = O4[k*16 + tx];   // 4 pixels
        float av[4] = {a.x, a.y, a.z, a.w};
        float bw[4] = {bb.x, bb.y, bb.z, bb.w};
        #pragma unroll
        for (int i = 0; i < 4; i++)
            #pragma unroll
            for (int j = 0; j < 4; j++)
                a2[i][j] = fmaf(av[i], bw[j], a2[i][j]);
    }
    #pragma unroll
    for (int i = 0; i < 4; i++) {
        int c = ty*4 + i;
        float4 v = make_float4(a2[i][0], a2[i][1], a2[i][2], a2[i][3]);
        *(float4*)(out + ((size_t)(b*Cn + c)*Hn + h)*Wn + w0 + tx*4) = v;
    }
}

// ---------------------------------------------------------------------------
extern "C" void kernel_launch(void* const* d_in, const int* in_sizes, int n_in,
                              void* d_out, int out_size) {
    const float* inp = (const float*)d_in[0];
    const float* Wv  = (const float*)d_in[1];
    const float* bv  = (const float*)d_in[2];
    const float* Wdw = (const float*)d_in[3];
    const float* bdw = (const float*)d_in[4];
    const float* Wom = (const float*)d_in[5];
    const float* bom = (const float*)d_in[6];
    const float* Wo  = (const float*)d_in[7];
    float* out = (float*)d_out;

    const int smB = 20416 * 4;   // 81664 B
    const int smC = 15104 * 4;   // 60416 B
    cudaFuncSetAttribute(k_offmask, cudaFuncAttributeMaxDynamicSharedMemorySize, smB);
    cudaFuncSetAttribute(k_sample,  cudaFuncAttributeMaxDynamicSharedMemorySize, smC);

    k_value<<<NTILE, 256>>>(inp, Wv, bv);
    k_offmask<<<NTILE, 256, smB>>>(inp, Wdw, bdw, Wom, bom);
    k_sample<<<NTILE, 256, smC>>>(Wo, out);
}